// round 7
// baseline (speedup 1.0000x reference)
#include <cuda_runtime.h>

// Fold: x (B=8, C=32, K1=8, K2=8, L=4096) -> out (B, C, H=260, W=260)
// kernel (8,8), stride (4,4), n = 64.
// Octo-gather: each thread computes 8 consecutive ow = 8p+{0..7}.
//   s=0..3: dj0=s   (j=2p  -> .x of v2 pair), dj1=s+4 (j=2p-1, scalar)
//   s=4..7: dj0=s-4 (j=2p+1-> .y of v2 pair), dj1=s   (j=2p,   scalar)
// dj0..3 planes loaded as 8B-aligned float2 (8 v2 loads); dj4..7 as 16
// scalars. 24 LDGs / 8 outputs, MLP ~24/thread, contiguous v4 stores.
// p=32 lone quad (ow 256..259) handled inline (only dj4..7 col 63 valid).

namespace {
constexpr int B = 8;
constexpr int C = 32;
constexpr int K = 8;
constexpr int N = 64;
constexpr int L = N * N;            // 4096
constexpr int H = 260;
constexpr int W = 260;
constexpr int PW = 33;              // 32 pairs-of-quads + 1 lone quad
constexpr int TOTAL_T = B * C * H * PW;  // 2,196,480 = 8580 * 256 exactly
}

__device__ __forceinline__ float ldg_256(const float* p) {
    float v;
    asm volatile("ld.global.nc.L2::256B.f32 %0, [%1];" : "=f"(v) : "l"(p));
    return v;
}

__device__ __forceinline__ float2 ldg2_256(const float* p) {
    float2 v;
    asm volatile("ld.global.nc.L2::256B.v2.f32 {%0, %1}, [%2];"
                 : "=f"(v.x), "=f"(v.y) : "l"(p));
    return v;
}

__global__ __launch_bounds__(256, 4) void fold_octo_kernel(
    const float* __restrict__ x, float* __restrict__ out) {
    int tid = blockIdx.x * blockDim.x + threadIdx.x;   // grid exact

    int p  = tid % PW;          // 0..32
    int t  = tid / PW;
    int oh = t % H;             // 0..259
    int bc = t / H;             // 0..255

    const float* __restrict__ xb = x + (long long)bc * (K * K * L);
    float* __restrict__ ob = out + (long long)bc * (H * W) + oh * W;

    int di0 = oh & 3;
    int di1 = di0 + 4;
    int i0  = oh >> 2;          // may be 64 (invalid) when oh >= 256
    int i1  = i0 - 1;           // may be -1 when oh < 4

    bool vi0 = i0 < N;
    bool vi1 = i1 >= 0;

    int row0 = i0 * N;
    int row1 = i1 * N;

    if (p < 32) {
        int cA = 2 * p;             // col pair {2p, 2p+1} for dj 0..3
        int cM = 2 * p - 1;         // col 2p-1 for dj 4..7 (invalid at p=0)
        bool vM0 = vi0 && (p >= 1);
        bool vM1 = vi1 && (p >= 1);

        float2 A0[4], A1[4];        // planes (di, dj=0..3), cols {2p,2p+1}
        float  M0[4], M1[4];        // planes (di, dj=4..7), col 2p-1
        float  Z0[4], Z1[4];        // planes (di, dj=4..7), col 2p
        const float2 zero2 = make_float2(0.f, 0.f);

#pragma unroll
        for (int r = 0; r < 4; r++) {
            A0[r] = vi0 ? ldg2_256(xb + (di0 * K + r) * L + row0 + cA) : zero2;
            A1[r] = vi1 ? ldg2_256(xb + (di1 * K + r) * L + row1 + cA) : zero2;
            M0[r] = vM0 ? ldg_256(xb + (di0 * K + r + 4) * L + row0 + cM) : 0.f;
            M1[r] = vM1 ? ldg_256(xb + (di1 * K + r + 4) * L + row1 + cM) : 0.f;
            Z0[r] = vi0 ? ldg_256(xb + (di0 * K + r + 4) * L + row0 + cA) : 0.f;
            Z1[r] = vi1 ? ldg_256(xb + (di1 * K + r + 4) * L + row1 + cA) : 0.f;
        }

        float4 o0, o1;
        // s = 0..3: A.x + M
        o0.x = (A0[0].x + M0[0]) + (A1[0].x + M1[0]);
        o0.y = (A0[1].x + M0[1]) + (A1[1].x + M1[1]);
        o0.z = (A0[2].x + M0[2]) + (A1[2].x + M1[2]);
        o0.w = (A0[3].x + M0[3]) + (A1[3].x + M1[3]);
        // s = 4..7: A.y + Z
        o1.x = (A0[0].y + Z0[0]) + (A1[0].y + Z1[0]);
        o1.y = (A0[1].y + Z0[1]) + (A1[1].y + Z1[1]);
        o1.z = (A0[2].y + Z0[2]) + (A1[2].y + Z1[2]);
        o1.w = (A0[3].y + Z0[3]) + (A1[3].y + Z1[3]);

        float4* ov = (float4*)(ob + 8 * p);
        ov[0] = o0;
        ov[1] = o1;
    } else {
        // lone quad: ow 256..259 -> only dj 4..7 at col 63 contribute
        float b0[4], b1[4];
#pragma unroll
        for (int r = 0; r < 4; r++) {
            b0[r] = vi0 ? ldg_256(xb + (di0 * K + r + 4) * L + row0 + 63) : 0.f;
            b1[r] = vi1 ? ldg_256(xb + (di1 * K + r + 4) * L + row1 + 63) : 0.f;
        }
        float4 o;
        o.x = b0[0] + b1[0];
        o.y = b0[1] + b1[1];
        o.z = b0[2] + b1[2];
        o.w = b0[3] + b1[3];
        *(float4*)(ob + 256) = o;
    }
}

extern "C" void kernel_launch(void* const* d_in, const int* in_sizes, int n_in,
                              void* d_out, int out_size) {
    const float* x = (const float*)d_in[0];
    float* out = (float*)d_out;
    int threads = 256;
    int blocks = TOTAL_T / threads;  // 8580 exactly
    fold_octo_kernel<<<blocks, threads>>>(x, out);
}

// round 8
// speedup vs baseline: 1.0125x; 1.0125x over previous
#include <cuda_runtime.h>

// Fold: x (B=8, C=32, K1=8, K2=8, L=4096) -> out (B, C, H=260, W=260)
// kernel (8,8), stride (4,4), n = 64.
// Warp-aligned quad-gather: block = 4 rows x 64 quads (qq = tid&63), so every
// warp covers 32 consecutive quads of ONE row -> all 16 warp-LDGs are
// single-128B-line. The lone quad (ow 256..259) of each row is handled by
// that row's qq==0 thread in the SAME block: its col-63 reads hit lines the
// qq=32..63 warp fetches, and its store completes the row within the block
// (avoids R5's re-fetch + split-dirty-line regression).

namespace {
constexpr int B = 8;
constexpr int C = 32;
constexpr int K = 8;
constexpr int N = 64;
constexpr int L = N * N;            // 4096
constexpr int H = 260;
constexpr int W = 260;
constexpr int ROWGRPS = H / 4;      // 65 groups of 4 rows
constexpr int BLOCKS = B * C * ROWGRPS;  // 16640
}

__device__ __forceinline__ float ldg_256(const float* p) {
    float v;
    asm volatile("ld.global.nc.L2::256B.f32 %0, [%1];" : "=f"(v) : "l"(p));
    return v;
}

__global__ __launch_bounds__(256) void fold_warprow_kernel(
    const float* __restrict__ x, float* __restrict__ out) {
    int blk = blockIdx.x;
    int rowgrp = blk % ROWGRPS;
    int bc = blk / ROWGRPS;

    int qq = threadIdx.x & 63;      // quad 0..63 within row
    int r  = threadIdx.x >> 6;      // row 0..3 within group
    int oh = rowgrp * 4 + r;        // 0..259

    const float* __restrict__ xb = x + (long long)bc * (K * K * L);
    float* __restrict__ ob = out + (long long)bc * (H * W) + oh * W;

    int di0 = oh & 3;
    int di1 = di0 + 4;
    int i0  = oh >> 2;              // may be 64 (invalid) when oh >= 256
    int i1  = i0 - 1;               // may be -1 when oh < 4

    bool vi0 = i0 < N;
    bool vi1 = i1 >= 0;
    bool vj1 = qq >= 1;

    int row0 = i0 * N;
    int row1 = i1 * N;

    bool v01 = vi0 && vj1;
    bool v11 = vi1 && vj1;

    float a[4], b[4], c[4], d[4];
#pragma unroll
    for (int j = 0; j < 4; j++) {
        a[j] = vi0 ? ldg_256(xb + (di0 * K + j) * L + row0 + qq) : 0.f;
        b[j] = v01 ? ldg_256(xb + (di0 * K + j + 4) * L + row0 + qq - 1) : 0.f;
        c[j] = vi1 ? ldg_256(xb + (di1 * K + j) * L + row1 + qq) : 0.f;
        d[j] = v11 ? ldg_256(xb + (di1 * K + j + 4) * L + row1 + qq - 1) : 0.f;
    }

    float4 o;
    o.x = (a[0] + b[0]) + (c[0] + d[0]);
    o.y = (a[1] + b[1]) + (c[1] + d[1]);
    o.z = (a[2] + b[2]) + (c[2] + d[2]);
    o.w = (a[3] + b[3]) + (c[3] + d[3]);

    ((float4*)ob)[qq] = o;

    // Lone quad (ow 256..259) for this row, handled by qq==0 thread.
    // Only dj=4..7 planes, column 63, contribute.
    if (qq == 0) {
        float e[4], f[4];
#pragma unroll
        for (int j = 0; j < 4; j++) {
            e[j] = vi0 ? ldg_256(xb + (di0 * K + j + 4) * L + row0 + 63) : 0.f;
            f[j] = vi1 ? ldg_256(xb + (di1 * K + j + 4) * L + row1 + 63) : 0.f;
        }
        float4 t;
        t.x = e[0] + f[0];
        t.y = e[1] + f[1];
        t.z = e[2] + f[2];
        t.w = e[3] + f[3];
        *(float4*)(ob + 256) = t;
    }
}

extern "C" void kernel_launch(void* const* d_in, const int* in_sizes, int n_in,
                              void* d_out, int out_size) {
    const float* x = (const float*)d_in[0];
    float* out = (float*)d_out;
    fold_warprow_kernel<<<BLOCKS, 256>>>(x, out);
}

// round 9
// speedup vs baseline: 1.0192x; 1.0066x over previous
#include <cuda_runtime.h>

// Fold: x (B=8, C=32, K1=8, K2=8, L=4096) -> out (B, C, H=260, W=260)
// kernel (8,8), stride (4,4), n = 64.
// Champion R4 quad-gather with 2D grid: blockIdx.y = bc (removes the
// 64-bit div chain for bc), blockIdx.x covers the 16900 quads of one
// (b,c) image. Reads provably single-use (planes dj0..3 at col q,
// dj4..7 at col q-1); traffic is the 322MB minimum; ~6.6TB/s HBM wall.

namespace {
constexpr int B = 8;
constexpr int C = 32;
constexpr int K = 8;
constexpr int N = 64;
constexpr int L = N * N;            // 4096
constexpr int H = 260;
constexpr int W = 260;
constexpr int QW = W / 4;           // 65 quads per row
constexpr int PER_BC = H * QW;      // 16900 quads per (b,c)
constexpr int BX = (PER_BC + 255) / 256;  // 67 blocks per bc
}

__device__ __forceinline__ float ldg_256(const float* p) {
    float v;
    asm volatile("ld.global.nc.L2::256B.f32 %0, [%1];" : "=f"(v) : "l"(p));
    return v;
}

__global__ __launch_bounds__(256) void fold_quad2d_kernel(
    const float* __restrict__ x, float* __restrict__ out) {
    int tq = blockIdx.x * 256 + threadIdx.x;   // quad index within this bc
    if (tq >= PER_BC) return;

    int bc = blockIdx.y;

    int q  = tq % QW;          // 0..64
    int oh = tq / QW;          // 0..259

    const float* __restrict__ xb = x + (long long)bc * (K * K * L);

    int di0 = oh & 3;
    int di1 = di0 + 4;
    int i0  = oh >> 2;          // may be 64 (invalid) when oh >= 256
    int i1  = i0 - 1;           // may be -1 when oh < 4

    bool vi0 = i0 < N;
    bool vi1 = i1 >= 0;
    bool vj0 = q < N;           // q may be 64 on last quad
    bool vj1 = q >= 1;

    int row0 = i0 * N;
    int row1 = i1 * N;

    bool v00 = vi0 && vj0, v01 = vi0 && vj1;
    bool v10 = vi1 && vj0, v11 = vi1 && vj1;

    float a[4], b[4], c[4], d[4];
#pragma unroll
    for (int r = 0; r < 4; r++) {
        a[r] = v00 ? ldg_256(xb + (di0 * K + r) * L + row0 + q) : 0.f;
        b[r] = v01 ? ldg_256(xb + (di0 * K + r + 4) * L + row0 + q - 1) : 0.f;
        c[r] = v10 ? ldg_256(xb + (di1 * K + r) * L + row1 + q) : 0.f;
        d[r] = v11 ? ldg_256(xb + (di1 * K + r + 4) * L + row1 + q - 1) : 0.f;
    }

    float4 o;
    o.x = (a[0] + b[0]) + (c[0] + d[0]);
    o.y = (a[1] + b[1]) + (c[1] + d[1]);
    o.z = (a[2] + b[2]) + (c[2] + d[2]);
    o.w = (a[3] + b[3]) + (c[3] + d[3]);

    float4* outv = (float4*)(out + (long long)bc * (H * W) + oh * W);
    outv[q] = o;
}

extern "C" void kernel_launch(void* const* d_in, const int* in_sizes, int n_in,
                              void* d_out, int out_size) {
    const float* x = (const float*)d_in[0];
    float* out = (float*)d_out;
    dim3 grid(BX, B * C);   // (67, 256)
    fold_quad2d_kernel<<<grid, 256>>>(x, out);
}